// round 4
// baseline (speedup 1.0000x reference)
#include <cuda_runtime.h>
#include <cuda_fp16.h>

// Sinkhorn on s[B=32, N=1024, M=1024], MAX_ITER=15, EPS=1e-4.
// Factored form: s_t = r_i * s0_ij * c_j over a one-time fp16 copy of s0
// (64 MB, L2-resident). ALL matrix passes are row-contiguous:
//   - column steps compute per-block column partials row-major; the last
//     block per batch (atomic counter) combines partials and updates c.
//   - fp32->fp16 conversion is fused into iteration 0's column pass.
//   - row steps are warp-per-row dot products with c staged in smem.

#define BB 32
#define NN 1024
#define MM 1024
#define EPSF 1e-4f
#define CBLK 16            // column-pass blocks per batch
#define CROWS (NN / CBLK)  // 64 rows per column-pass block
#define NCOL_IT 8          // number of column iterations (it = 0,2,...,14)

__device__ __half2 g_h[(size_t)BB * NN * MM / 2];   // 64 MB fp16 copy
__device__ float g_r[BB * NN];
__device__ float g_c[BB * MM];
__device__ float g_part[(size_t)BB * CBLK * MM];    // 2 MB partials
__device__ int g_cnt[NCOL_IT * BB];                 // zero-init; self-reset

// ---------------------------------------------------------------------------
// Shared epilogue: last block of batch b combines CBLK partials (fixed order)
// and updates c_j <- c_old_j / (c_old_j * P_j + eps). Threadfence-reduction
// pattern; counter self-resets so graph replays start clean.
__device__ __forceinline__ void col_epilogue(int b, int slot, bool first) {
    __syncthreads();
    __threadfence();
    __shared__ int s_last;
    if (threadIdx.x == 0)
        s_last = atomicAdd(&g_cnt[slot * BB + b], 1);
    __syncthreads();
    if (s_last == CBLK - 1) {
        __threadfence();  // order with producers' fenced writes
        const int j = threadIdx.x * 4;  // 4 columns per thread
        float4 p = make_float4(0.f, 0.f, 0.f, 0.f);
#pragma unroll
        for (int k = 0; k < CBLK; k++) {
            const float4 v =
                *(const float4*)&g_part[((size_t)(b * CBLK + k)) * MM + j];
            p.x += v.x; p.y += v.y; p.z += v.z; p.w += v.w;
        }
        float4 c = first ? make_float4(1.f, 1.f, 1.f, 1.f)
                         : *(const float4*)&g_c[b * MM + j];
        c.x = c.x / fmaf(c.x, p.x, EPSF);
        c.y = c.y / fmaf(c.y, p.y, EPSF);
        c.z = c.z / fmaf(c.z, p.z, EPSF);
        c.w = c.w / fmaf(c.w, p.w, EPSF);
        *(float4*)&g_c[b * MM + j] = c;
        if (threadIdx.x == 0) g_cnt[slot * BB + b] = 0;
    }
}

// ---------------------------------------------------------------------------
// Iteration 0 (column step with r=1), fused with fp32 -> fp16 conversion.
// grid: (CBLK, BB), block 256. Block owns 64 rows; thread owns 4 columns.
__global__ void fused_conv_col0_kernel(const float* __restrict__ s) {
    const int b = blockIdx.y;
    const int r0 = blockIdx.x * CROWS;
    const int j = threadIdx.x * 4;

    const float* sp = s + (size_t)(b * NN + r0) * MM + j;
    __half2* hp = (__half2*)(g_h + (size_t)(b * NN + r0) * (MM / 2) + j / 2);

    float4 acc = make_float4(0.f, 0.f, 0.f, 0.f);
#pragma unroll 4
    for (int i = 0; i < CROWS; i++) {
        float4 v = *(const float4*)(sp + (size_t)i * MM);
        __half2 h0 = __floats2half2_rn(v.x, v.y);
        __half2 h1 = __floats2half2_rn(v.z, v.w);
        uint2 o;
        o.x = *(unsigned*)&h0;
        o.y = *(unsigned*)&h1;
        *(uint2*)(hp + (size_t)i * (MM / 2)) = o;
        acc.x += v.x; acc.y += v.y; acc.z += v.z; acc.w += v.w;
    }
    *(float4*)&g_part[((size_t)(b * CBLK + blockIdx.x)) * MM + j] = acc;

    col_epilogue(b, 0, true);
}

// ---------------------------------------------------------------------------
// Column step over fp16 copy (row-contiguous):
//   partials of P_j = sum_i r_i * s0_ij over the block's 64 rows.
// grid: (CBLK, BB), block 256. Thread owns 4 columns (one uint2 per row).
__global__ void col_step_kernel(int slot) {
    const int b = blockIdx.y;
    const int r0 = blockIdx.x * CROWS;
    const int j = threadIdx.x * 4;

    __shared__ float sr[CROWS];
    if (threadIdx.x < CROWS) sr[threadIdx.x] = g_r[b * NN + r0 + threadIdx.x];
    __syncthreads();

    const uint2* hp =
        (const uint2*)(g_h + (size_t)(b * NN + r0) * (MM / 2)) + j / 4;

    float4 acc = make_float4(0.f, 0.f, 0.f, 0.f);
#pragma unroll 8
    for (int i = 0; i < CROWS; i++) {
        uint2 v = hp[(size_t)i * (MM / 4)];
        float rw = sr[i];
        float2 f0 = __half22float2(*(__half2*)&v.x);
        float2 f1 = __half22float2(*(__half2*)&v.y);
        acc.x = fmaf(rw, f0.x, acc.x);
        acc.y = fmaf(rw, f0.y, acc.y);
        acc.z = fmaf(rw, f1.x, acc.z);
        acc.w = fmaf(rw, f1.y, acc.w);
    }
    *(float4*)&g_part[((size_t)(b * CBLK + blockIdx.x)) * MM + j] = acc;

    col_epilogue(b, slot, false);
}

// ---------------------------------------------------------------------------
// Row step: Q_i = sum_j s0[b,i,j]*c[b,j];  r_i <- r_old/(r_old*Q_i + eps)
// grid: (NN/8, BB), block 256 = 8 warps, one row per warp (128 uint4/row).
__global__ void row_step_kernel(int first) {
    const int b = blockIdx.y;
    const int warp = threadIdx.x >> 5;
    const int lane = threadIdx.x & 31;
    const int i = blockIdx.x * 8 + warp;

    __shared__ float sh_c[MM];
    for (int k = threadIdx.x; k < MM; k += 256)
        sh_c[k] = g_c[b * MM + k];
    __syncthreads();

    const uint4* hp = (const uint4*)(g_h + ((size_t)(b * NN + i)) * (MM / 2));

    float acc = 0.f;
#pragma unroll
    for (int k = 0; k < 4; k++) {  // 4 x 16B per lane = 32 halfs
        int v4 = k * 32 + lane;
        uint4 v = hp[v4];
        int jj = v4 * 8;
        float2 f0 = __half22float2(*(__half2*)&v.x);
        float2 f1 = __half22float2(*(__half2*)&v.y);
        float2 f2 = __half22float2(*(__half2*)&v.z);
        float2 f3 = __half22float2(*(__half2*)&v.w);
        acc = fmaf(f0.x, sh_c[jj + 0], acc);
        acc = fmaf(f0.y, sh_c[jj + 1], acc);
        acc = fmaf(f1.x, sh_c[jj + 2], acc);
        acc = fmaf(f1.y, sh_c[jj + 3], acc);
        acc = fmaf(f2.x, sh_c[jj + 4], acc);
        acc = fmaf(f2.y, sh_c[jj + 5], acc);
        acc = fmaf(f3.x, sh_c[jj + 6], acc);
        acc = fmaf(f3.y, sh_c[jj + 7], acc);
    }
#pragma unroll
    for (int o = 16; o > 0; o >>= 1)
        acc += __shfl_xor_sync(0xffffffffu, acc, o);

    if (lane == 0) {
        float r = first ? 1.0f : g_r[b * NN + i];
        g_r[b * NN + i] = r / fmaf(r, acc, EPSF);
    }
}

// ---------------------------------------------------------------------------
// Final: out = r_i * s0_ij * c_j from the ORIGINAL fp32 s0 (full precision).
// grid: (NN/8, BB), 256 threads; block covers 8 rows (256 float4 per row).
__global__ void finalize_kernel(const float* __restrict__ s,
                                float* __restrict__ out) {
    const int b = blockIdx.y;
    const int i0 = blockIdx.x * 8;

    __shared__ float4 sh_c4[MM / 4];
    {
        const float4* cg = (const float4*)(g_c + (size_t)b * MM);
        sh_c4[threadIdx.x] = cg[threadIdx.x];
    }
    __syncthreads();

    const float4 c4 = sh_c4[threadIdx.x];

#pragma unroll
    for (int w = 0; w < 8; w++) {
        const int i = i0 + w;
        const float r = g_r[b * NN + i];
        const float4* sp =
            (const float4*)(s + (size_t)b * NN * MM + (size_t)i * MM);
        float4* op = (float4*)(out + (size_t)b * NN * MM + (size_t)i * MM);
        float4 v = sp[threadIdx.x];
        float4 o;
        o.x = r * v.x * c4.x;
        o.y = r * v.y * c4.y;
        o.z = r * v.z * c4.z;
        o.w = r * v.w * c4.w;
        op[threadIdx.x] = o;
    }
}

// ---------------------------------------------------------------------------
extern "C" void kernel_launch(void* const* d_in, const int* in_sizes, int n_in,
                              void* d_out, int out_size) {
    const float* s = (const float*)d_in[0];
    float* out = (float*)d_out;

    // it = 0 (column step, r = 1) fused with fp16 conversion
    fused_conv_col0_kernel<<<dim3(CBLK, BB), 256>>>(s);

    for (int it = 1; it < 15; it++) {
        if (it & 1) {
            row_step_kernel<<<dim3(NN / 8, BB), 256>>>(it == 1 ? 1 : 0);
        } else {
            col_step_kernel<<<dim3(CBLK, BB), 256>>>(it / 2);
        }
    }

    finalize_kernel<<<dim3(NN / 8, BB), 256>>>(s, out);
}

// round 5
// speedup vs baseline: 1.5325x; 1.5325x over previous
#include <cuda_runtime.h>
#include <cuda_fp16.h>

// Sinkhorn on s[B=32, N=1024, M=1024], MAX_ITER=15, EPS=1e-4.
//
// Single persistent kernel. Factored form s_t = r_i * s0_ij * c_j.
// Block k of batch b owns rows [64k, 64k+64) for ALL phases, so the fp16
// copy of its slice is block-private. Cross-block data is only the 4KB
// column-partial vector per block per column iteration (double-buffered),
// synchronized by a batch-local (16-block) monotonic barrier.
// r lives in block smem; c is redundantly recomputed into every block's
// smem from the partials (identical fixed-order arithmetic in all blocks).

#define BB 32
#define NN 1024
#define MM 1024
#define EPSF 1e-4f
#define KB_ 16            // blocks per batch
#define RPB (NN / KB_)    // 64 rows per block

__device__ __half2 g_h[(size_t)BB * NN * MM / 2];           // 64 MB fp16 copy
__device__ float g_part[2][BB * KB_ * MM];                  // double-buffered
__device__ int g_cnt2[BB];                                  // zero-init
__device__ int g_flag[BB];                                  // monotonic, persists

// ---------------------------------------------------------------------------
// Batch-local barrier: 16 blocks of batch b. Monotonic target continues from
// the persisted flag value, so graph replays need no reset.
__device__ __forceinline__ void batch_barrier(int b, int& nextv) {
    __threadfence();          // make this thread's prior global writes visible
    __syncthreads();
    nextv += 1;
    if (threadIdx.x == 0) {
        int old = atomicAdd(&g_cnt2[b], 1);
        if (old == KB_ - 1) {
            atomicExch(&g_cnt2[b], 0);
            __threadfence();
            *(volatile int*)&g_flag[b] = nextv;
        } else {
            while (*(volatile int*)&g_flag[b] - nextv < 0) __nanosleep(32);
        }
        __threadfence();
    }
    __syncthreads();
}

// ---------------------------------------------------------------------------
__global__ void __launch_bounds__(256, 4)
sinkhorn_kernel(const float* __restrict__ s, float* __restrict__ out) {
    const int bx = blockIdx.x;
    const int b = bx >> 4;        // batch
    const int k = bx & (KB_ - 1); // block within batch
    const int tid = threadIdx.x;
    const int i0 = k * RPB;       // first owned row

    __shared__ float sc[MM];      // column scaling c (full vector)
    __shared__ float sr[RPB];     // row scaling r (own rows only)

    // Monotonic barrier base: flag only advances at barriers, and no barrier
    // completes until every block has read its base, so all reads agree.
    int nextv;
    {
        // all threads read the same value (flag static until first barrier)
        nextv = *(volatile int*)&g_flag[b];
    }

    const size_t row0 = (size_t)(b * NN + i0);

    // ---------------- it = 0: fp32->fp16 conversion + column partials (r=1)
    {
        const float* sp = s + row0 * MM + tid * 4;
        __half2* hp = g_h + row0 * (MM / 2) + tid * 2;
        float4 acc = make_float4(0.f, 0.f, 0.f, 0.f);
#pragma unroll 4
        for (int i = 0; i < RPB; i++) {
            float4 v = *(const float4*)(sp + (size_t)i * MM);
            __half2 h0 = __floats2half2_rn(v.x, v.y);
            __half2 h1 = __floats2half2_rn(v.z, v.w);
            uint2 o;
            o.x = *(unsigned*)&h0;
            o.y = *(unsigned*)&h1;
            *(uint2*)(hp + (size_t)i * (MM / 2)) = o;
            acc.x += v.x; acc.y += v.y; acc.z += v.z; acc.w += v.w;
        }
        *(float4*)&g_part[0][((size_t)(b * KB_ + k)) * MM + tid * 4] = acc;
    }
    batch_barrier(b, nextv);

    // Reduce partials (buffer 0) -> c, c_old = 1. All blocks redundantly.
    {
        const int j = tid * 4;
        float4 p = make_float4(0.f, 0.f, 0.f, 0.f);
#pragma unroll
        for (int q = 0; q < KB_; q++) {
            const float4 v = __ldcg(
                (const float4*)&g_part[0][((size_t)(b * KB_ + q)) * MM + j]);
            p.x += v.x; p.y += v.y; p.z += v.z; p.w += v.w;
        }
        sc[j + 0] = 1.0f / (p.x + EPSF);
        sc[j + 1] = 1.0f / (p.y + EPSF);
        sc[j + 2] = 1.0f / (p.z + EPSF);
        sc[j + 3] = 1.0f / (p.w + EPSF);
    }
    __syncthreads();

    // ---------------- 7 x (row step it=2h+1, col step it=2h+2)
    const int warp = tid >> 5;
    const int lane = tid & 31;

    for (int half = 0; half < 7; half++) {
        // ---- row step: Q_i = sum_j h_ij * c_j ; r_i <- r_old/(r_old*Q+eps)
#pragma unroll
        for (int rr = 0; rr < RPB / 8; rr++) {   // 8 rows per warp
            const int i = warp * (RPB / 8) + rr;
            const uint4* hp =
                (const uint4*)(g_h + (row0 + i) * (MM / 2));
            float acc = 0.f;
#pragma unroll
            for (int kk = 0; kk < 4; kk++) {
                int v4 = kk * 32 + lane;
                uint4 v = hp[v4];
                int jj = v4 * 8;
                float2 f0 = __half22float2(*(__half2*)&v.x);
                float2 f1 = __half22float2(*(__half2*)&v.y);
                float2 f2 = __half22float2(*(__half2*)&v.z);
                float2 f3 = __half22float2(*(__half2*)&v.w);
                acc = fmaf(f0.x, sc[jj + 0], acc);
                acc = fmaf(f0.y, sc[jj + 1], acc);
                acc = fmaf(f1.x, sc[jj + 2], acc);
                acc = fmaf(f1.y, sc[jj + 3], acc);
                acc = fmaf(f2.x, sc[jj + 4], acc);
                acc = fmaf(f2.y, sc[jj + 5], acc);
                acc = fmaf(f3.x, sc[jj + 6], acc);
                acc = fmaf(f3.y, sc[jj + 7], acc);
            }
#pragma unroll
            for (int o = 16; o > 0; o >>= 1)
                acc += __shfl_xor_sync(0xffffffffu, acc, o);
            if (lane == 0) {
                float r = (half == 0) ? 1.0f : sr[i];
                sr[i] = r / fmaf(r, acc, EPSF);
            }
        }
        __syncthreads();

        // ---- col step partials: P_j += r_i * h_ij over own rows
        const int buf = (half + 1) & 1;
        {
            const uint2* hp =
                (const uint2*)(g_h + row0 * (MM / 2)) + tid;  // 4 cols/thread
            float4 acc = make_float4(0.f, 0.f, 0.f, 0.f);
#pragma unroll 8
            for (int i = 0; i < RPB; i++) {
                uint2 v = hp[(size_t)i * (MM / 4)];
                float rw = sr[i];
                float2 f0 = __half22float2(*(__half2*)&v.x);
                float2 f1 = __half22float2(*(__half2*)&v.y);
                acc.x = fmaf(rw, f0.x, acc.x);
                acc.y = fmaf(rw, f0.y, acc.y);
                acc.z = fmaf(rw, f1.x, acc.z);
                acc.w = fmaf(rw, f1.y, acc.w);
            }
            *(float4*)&g_part[buf][((size_t)(b * KB_ + k)) * MM + tid * 4] =
                acc;
        }
        batch_barrier(b, nextv);

        // ---- reduce partials -> c update (all blocks, identical order)
        {
            const int j = tid * 4;
            float4 p = make_float4(0.f, 0.f, 0.f, 0.f);
#pragma unroll
            for (int q = 0; q < KB_; q++) {
                const float4 v = __ldcg((const float4*)
                    &g_part[buf][((size_t)(b * KB_ + q)) * MM + j]);
                p.x += v.x; p.y += v.y; p.z += v.z; p.w += v.w;
            }
            float4 c = *(float4*)&sc[j];
            c.x = c.x / fmaf(c.x, p.x, EPSF);
            c.y = c.y / fmaf(c.y, p.y, EPSF);
            c.z = c.z / fmaf(c.z, p.z, EPSF);
            c.w = c.w / fmaf(c.w, p.w, EPSF);
            *(float4*)&sc[j] = c;
        }
        __syncthreads();
    }

    // ---------------- finalize: out = r_i * s0_ij * c_j (fp32 source)
    {
        const int j = tid * 4;
        const float4 c4 = *(float4*)&sc[j];
        const float* sp = s + row0 * MM + j;
        float* op = out + row0 * MM + j;
#pragma unroll 4
        for (int i = 0; i < RPB; i++) {
            const float r = sr[i];
            float4 v = *(const float4*)(sp + (size_t)i * MM);
            float4 o;
            o.x = r * v.x * c4.x;
            o.y = r * v.y * c4.y;
            o.z = r * v.z * c4.z;
            o.w = r * v.w * c4.w;
            *(float4*)(op + (size_t)i * MM) = o;
        }
    }
}

// ---------------------------------------------------------------------------
extern "C" void kernel_launch(void* const* d_in, const int* in_sizes, int n_in,
                              void* d_out, int out_size) {
    const float* s = (const float*)d_in[0];
    float* out = (float*)d_out;
    sinkhorn_kernel<<<BB * KB_, 256>>>(s, out);
}